// round 1
// baseline (speedup 1.0000x reference)
#include <cuda_runtime.h>

#define NQ    16384
#define KP    32
#define C     512
#define HREF  512
#define HCONF 256
#define NSTEPS 3

// ---------------- scratch (__device__ globals; no allocation allowed) ----------------
__device__ float g_wmean[NSTEPS * KP * C];   // raw soft^T @ qf, then finalized in place
__device__ float g_wsum [NSTEPS * KP];
__device__ float g_h    [KP * HREF];         // MLP hidden pre-activation (incl b1)
__device__ float g_hp   [KP * HCONF];
__device__ float g_hq   [NQ * HCONF];        // 16 MB
__device__ float g_conf [KP];

// ---------------- init: zero accumulators, seed refined = prototypes ----------------
__global__ void init_kernel(const float* __restrict__ proto, float* __restrict__ out) {
    int idx = blockIdx.x * blockDim.x + threadIdx.x;   // grid covers NSTEPS*KP*C = 49152
    if (idx < NSTEPS * KP * C) g_wmean[idx] = 0.f;
    if (idx < NSTEPS * KP)     g_wsum[idx]  = 0.f;
    if (idx < KP)              g_conf[idx]  = 0.f;
    if (idx < KP * C)          out[idx]     = proto[idx];   // refined lives in d_out[0:16384]
}

// ---------------- wmean: for all 3 temperatures, soft^T @ qf via block-partial outer products ----
// grid (NQ/128, 3), block 256. Each block: 128 queries, full 32x512 accumulator in registers.
__global__ void wmean_kernel(const float* __restrict__ qd, const float* __restrict__ qf) {
    __shared__ float s_soft[128][KP];   // 16 KB
    __shared__ float s_qf[8][C];        // 16 KB
    const int step  = blockIdx.y;
    const int qbase = blockIdx.x * 128;
    const int tid   = threadIdx.x;

    if (tid < 128) {
        const float inv_t = 1.0f / (float)(step + 1);
        const float* row = qd + (size_t)(qbase + tid) * KP;
        float v[KP];
        float m = -1e30f;
#pragma unroll
        for (int i = 0; i < KP; i++) { v[i] = -row[i] * inv_t; m = fmaxf(m, v[i]); }
        float s = 0.f;
#pragma unroll
        for (int i = 0; i < KP; i++) { v[i] = __expf(v[i] - m); s += v[i]; }
        const float inv = 1.0f / s;
#pragma unroll
        for (int i = 0; i < KP; i++) s_soft[tid][i] = v[i] * inv;
    }
    __syncthreads();

    if (tid < KP) {  // partial column sums for wsum
        float s = 0.f;
        for (int q = 0; q < 128; q++) s += s_soft[q][tid];
        atomicAdd(&g_wsum[step * KP + tid], s);
    }

    const int kg = tid >> 6;    // 0..3  -> 8 k's
    const int cg = tid & 63;    // 0..63 -> 8 c's
    float acc[64];
#pragma unroll
    for (int i = 0; i < 64; i++) acc[i] = 0.f;

    for (int qc = 0; qc < 16; ++qc) {
        __syncthreads();
        const float4* src = (const float4*)(qf + (size_t)(qbase + qc * 8) * C);
        float4* dst = (float4*)&s_qf[0][0];
#pragma unroll
        for (int r = 0; r < 4; r++) dst[tid + 256 * r] = src[tid + 256 * r];
        __syncthreads();
#pragma unroll
        for (int qq = 0; qq < 8; ++qq) {
            const int q = qc * 8 + qq;
            float4 s0 = *(const float4*)&s_soft[q][kg * 8];
            float4 s1 = *(const float4*)&s_soft[q][kg * 8 + 4];
            float4 f0 = *(const float4*)&s_qf[qq][cg * 8];
            float4 f1 = *(const float4*)&s_qf[qq][cg * 8 + 4];
            float sv[8] = {s0.x, s0.y, s0.z, s0.w, s1.x, s1.y, s1.z, s1.w};
            float fv[8] = {f0.x, f0.y, f0.z, f0.w, f1.x, f1.y, f1.z, f1.w};
#pragma unroll
            for (int a = 0; a < 8; a++)
#pragma unroll
                for (int b = 0; b < 8; b++)
                    acc[a * 8 + b] = fmaf(sv[a], fv[b], acc[a * 8 + b]);
        }
    }
    float* base = g_wmean + (size_t)(step * KP + kg * 8) * C + cg * 8;
#pragma unroll
    for (int a = 0; a < 8; a++)
#pragma unroll
        for (int b = 0; b < 8; b++)
            atomicAdd(base + a * C + b, acc[a * 8 + b]);
}

// ---------------- wmean finalize: divide by max(wsum, 1e-6) ----------------
__global__ void wmean_fin_kernel() {
    int idx = blockIdx.x * blockDim.x + threadIdx.x;   // 49152
    if (idx < NSTEPS * KP * C) {
        float w = fmaxf(g_wsum[idx / C], 1e-6f);
        g_wmean[idx] = g_wmean[idx] / w;
    }
}

// ---------------- MLP layer 1: h_raw = concat @ W1 + b1 (per prototype block) ----------------
__global__ void gemm1_kernel(const float* __restrict__ refined, const float* __restrict__ W1,
                             const float* __restrict__ b1, int step) {
    const int k = blockIdx.x;       // 0..31
    const int tid = threadIdx.x;    // 128
    __shared__ float a[2 * C];
#pragma unroll
    for (int r = 0; r < 4; r++) a[tid + 128 * r]     = refined[k * C + tid + 128 * r];
#pragma unroll
    for (int r = 0; r < 4; r++) a[C + tid + 128 * r] = g_wmean[(size_t)(step * KP + k) * C + tid + 128 * r];
    __syncthreads();

    float4 acc = make_float4(0.f, 0.f, 0.f, 0.f);
#pragma unroll 4
    for (int i = 0; i < 2 * C; i++) {
        const float av = a[i];
        const float4 w = *(const float4*)(W1 + (size_t)i * HREF + tid * 4);
        acc.x = fmaf(av, w.x, acc.x); acc.y = fmaf(av, w.y, acc.y);
        acc.z = fmaf(av, w.z, acc.z); acc.w = fmaf(av, w.w, acc.w);
    }
    const float4 b = *(const float4*)(b1 + tid * 4);
    acc.x += b.x; acc.y += b.y; acc.z += b.z; acc.w += b.w;
    *(float4*)(g_h + k * HREF + tid * 4) = acc;
}

// ---------------- MLP layer 2: refined += 0.1*(relu(h_raw) @ W2 + b2) ----------------
__global__ void gemm2_kernel(float* __restrict__ refined, const float* __restrict__ W2,
                             const float* __restrict__ b2) {
    const int k = blockIdx.x;
    const int tid = threadIdx.x;    // 128
    __shared__ float h[HREF];
#pragma unroll
    for (int r = 0; r < 4; r++) h[tid + 128 * r] = fmaxf(g_h[k * HREF + tid + 128 * r], 0.f);
    __syncthreads();

    float4 acc = make_float4(0.f, 0.f, 0.f, 0.f);
#pragma unroll 4
    for (int j = 0; j < HREF; j++) {
        const float hv = h[j];
        const float4 w = *(const float4*)(W2 + (size_t)j * C + tid * 4);
        acc.x = fmaf(hv, w.x, acc.x); acc.y = fmaf(hv, w.y, acc.y);
        acc.z = fmaf(hv, w.z, acc.z); acc.w = fmaf(hv, w.w, acc.w);
    }
    const float4 b = *(const float4*)(b2 + tid * 4);
    float4 cur = *(float4*)(refined + k * C + tid * 4);
    cur.x += 0.1f * (acc.x + b.x); cur.y += 0.1f * (acc.y + b.y);
    cur.z += 0.1f * (acc.z + b.z); cur.w += 0.1f * (acc.w + b.w);
    *(float4*)(refined + k * C + tid * 4) = cur;
}

// ---------------- hp = prototypes @ Wc1[:C] ----------------
__global__ void hp_kernel(const float* __restrict__ proto, const float* __restrict__ Wc1) {
    const int k = blockIdx.x;       // 0..31
    const int tid = threadIdx.x;    // 256
    __shared__ float p[C];
    p[tid] = proto[k * C + tid];
    p[tid + 256] = proto[k * C + tid + 256];
    __syncthreads();
    float acc = 0.f;
#pragma unroll 4
    for (int c = 0; c < C; c++) acc = fmaf(p[c], Wc1[(size_t)c * HCONF + tid], acc);
    g_hp[k * HCONF + tid] = acc;
}

// ---------------- hq = qf @ Wc1[C:]  (M=16384, N=256, K=512 tiled fp32 GEMM) ----------------
__global__ void hq_kernel(const float* __restrict__ qf, const float* __restrict__ Wc1) {
    const float* __restrict__ B = Wc1 + (size_t)C * HCONF;   // Wq, (512 x 256) row-major
    __shared__ float As[16][128];   // 8 KB (k-major)
    __shared__ float Bs[16][64];    // 4 KB

    const int m0 = blockIdx.x * 128;
    const int n0 = blockIdx.y * 64;
    const int tid = threadIdx.x;    // 256
    const int tm = tid & 15;        // 16 m-groups of 8
    const int tn = tid >> 4;        // 16 n-groups of 4

    const int la_m = tid >> 2;          // 0..63
    const int la_k = (tid & 3) * 4;     // 0,4,8,12
    const int lb_c = tid >> 4;          // 0..15
    const int lb_h = (tid & 15) * 4;    // 0..60

    float4 acc[8];
#pragma unroll
    for (int i = 0; i < 8; i++) acc[i] = make_float4(0.f, 0.f, 0.f, 0.f);

    for (int kk = 0; kk < C; kk += 16) {
        __syncthreads();
        float4 a0 = *(const float4*)(qf + (size_t)(m0 + la_m) * C + kk + la_k);
        float4 a1 = *(const float4*)(qf + (size_t)(m0 + la_m + 64) * C + kk + la_k);
        As[la_k + 0][la_m] = a0.x; As[la_k + 1][la_m] = a0.y;
        As[la_k + 2][la_m] = a0.z; As[la_k + 3][la_m] = a0.w;
        As[la_k + 0][la_m + 64] = a1.x; As[la_k + 1][la_m + 64] = a1.y;
        As[la_k + 2][la_m + 64] = a1.z; As[la_k + 3][la_m + 64] = a1.w;
        *(float4*)&Bs[lb_c][lb_h] = *(const float4*)(B + (size_t)(kk + lb_c) * HCONF + n0 + lb_h);
        __syncthreads();
#pragma unroll
        for (int k2 = 0; k2 < 16; k2++) {
            const float4 am0 = *(const float4*)&As[k2][tm * 8];
            const float4 am1 = *(const float4*)&As[k2][tm * 8 + 4];
            const float4 bn  = *(const float4*)&Bs[k2][tn * 4];
            const float am[8] = {am0.x, am0.y, am0.z, am0.w, am1.x, am1.y, am1.z, am1.w};
#pragma unroll
            for (int i = 0; i < 8; i++) {
                acc[i].x = fmaf(am[i], bn.x, acc[i].x);
                acc[i].y = fmaf(am[i], bn.y, acc[i].y);
                acc[i].z = fmaf(am[i], bn.z, acc[i].z);
                acc[i].w = fmaf(am[i], bn.w, acc[i].w);
            }
        }
    }
#pragma unroll
    for (int i = 0; i < 8; i++)
        *(float4*)(g_hq + (size_t)(m0 + tm * 8 + i) * HCONF + n0 + tn * 4) = acc[i];
}

// ---------------- conf: per-(q,k) fused relu-dot + sigmoid, never materializing hidden ----------------
__global__ void conf_kernel(const float* __restrict__ Wc2, const float* __restrict__ bc1,
                            const float* __restrict__ bc2) {
    __shared__ float s_hp[KP][HCONF];    // 32 KB
    __shared__ float s_part[8][KP];
    const int tid  = threadIdx.x;        // 256
    const int lane = tid & 31;
    const int warp = tid >> 5;

    float* hpflat = &s_hp[0][0];
#pragma unroll
    for (int r = 0; r < 32; r++) hpflat[tid + 256 * r] = g_hp[tid + 256 * r];

    float wc2r[8], bcr[8];
#pragma unroll
    for (int j = 0; j < 8; j++) {
        wc2r[j] = Wc2[lane + 32 * j];
        bcr[j]  = bc1[lane + 32 * j];
    }
    const float bc2v = bc2[0];
    __syncthreads();

    float conf_acc = 0.f;
    const int nwarps = gridDim.x * 8;
    for (int q = blockIdx.x * 8 + warp; q < NQ; q += nwarps) {
        float a[8];
#pragma unroll
        for (int j = 0; j < 8; j++) a[j] = g_hq[(size_t)q * HCONF + lane + 32 * j] + bcr[j];
#pragma unroll 4
        for (int k = 0; k < KP; k++) {
            float s = 0.f;
#pragma unroll
            for (int j = 0; j < 8; j++) {
                float t = fmaxf(s_hp[k][lane + 32 * j] + a[j], 0.f);
                s = fmaf(t, wc2r[j], s);
            }
            s += __shfl_xor_sync(0xffffffffu, s, 16);
            s += __shfl_xor_sync(0xffffffffu, s, 8);
            s += __shfl_xor_sync(0xffffffffu, s, 4);
            s += __shfl_xor_sync(0xffffffffu, s, 2);
            s += __shfl_xor_sync(0xffffffffu, s, 1);
            const float sig = 1.0f / (1.0f + __expf(-(s + bc2v)));
            if (k == lane) conf_acc += sig;
        }
    }
    s_part[warp][lane] = conf_acc;
    __syncthreads();
    if (tid < KP) {
        float t = 0.f;
#pragma unroll
        for (int w = 0; w < 8; w++) t += s_part[w][tid];
        atomicAdd(&g_conf[tid], t);
    }
}

// ---------------- final: confidence mean ----------------
__global__ void conf_fin_kernel(float* __restrict__ out) {
    int tid = threadIdx.x;
    if (tid < KP) out[KP * C + tid] = g_conf[tid] * (1.0f / (float)NQ);
}

// ---------------- launch ----------------
extern "C" void kernel_launch(void* const* d_in, const int* in_sizes, int n_in,
                              void* d_out, int out_size) {
    const float* proto = (const float*)d_in[0];
    const float* qf    = (const float*)d_in[1];
    const float* qd    = (const float*)d_in[2];
    const float* W1    = (const float*)d_in[3];
    const float* b1    = (const float*)d_in[4];
    const float* W2    = (const float*)d_in[5];
    const float* b2    = (const float*)d_in[6];
    const float* Wc1   = (const float*)d_in[7];
    const float* bc1   = (const float*)d_in[8];
    const float* Wc2   = (const float*)d_in[9];
    const float* bc2   = (const float*)d_in[10];
    float* out = (float*)d_out;

    init_kernel<<<192, 256>>>(proto, out);
    wmean_kernel<<<dim3(NQ / 128, NSTEPS), 256>>>(qd, qf);
    wmean_fin_kernel<<<192, 256>>>();
    for (int t = 0; t < NSTEPS; t++) {
        gemm1_kernel<<<KP, 128>>>(out, W1, b1, t);
        gemm2_kernel<<<KP, 128>>>(out, W2, b2);
    }
    hp_kernel<<<KP, 256>>>(proto, Wc1);
    hq_kernel<<<dim3(NQ / 128, HCONF / 64), 256>>>(qf, Wc1);
    conf_kernel<<<256, 256>>>(Wc2, bc1, bc2);
    conf_fin_kernel<<<1, 32>>>(out);
}

// round 2
// speedup vs baseline: 1.6695x; 1.6695x over previous
#include <cuda_runtime.h>

#define NQ    16384
#define KP    32
#define C     512
#define HREF  512
#define HCONF 256
#define NSTEPS 3

// ---------------- scratch (__device__ globals; no allocation allowed) ----------------
__device__ float g_wmean[NSTEPS * KP * C];   // raw soft^T @ qf, then finalized in place
__device__ float g_wsum [NSTEPS * KP];
__device__ float g_h    [NSTEPS * KP * HREF];// MLP hidden pre-activation (no bias), per step
__device__ float g_hp   [KP * HCONF];
__device__ float g_hq   [NQ * HCONF];        // 16 MB
__device__ float g_conf [KP];

// ---------------- init: zero accumulators, seed refined = prototypes ----------------
__global__ void init_kernel(const float* __restrict__ proto, float* __restrict__ out) {
    int idx = blockIdx.x * blockDim.x + threadIdx.x;   // 49152 threads
    if (idx < NSTEPS * KP * C)    g_wmean[idx] = 0.f;
    if (idx < NSTEPS * KP * HREF) g_h[idx]     = 0.f;
    if (idx < KP * HCONF)         g_hp[idx]    = 0.f;
    if (idx < NSTEPS * KP)        g_wsum[idx]  = 0.f;
    if (idx < KP)                 g_conf[idx]  = 0.f;
    if (idx < KP * C)             out[idx]     = proto[idx];   // refined lives in d_out[0:16384]
}

// ---------------- wmean: for all 3 temperatures, soft^T @ qf via block-partial outer products ----
// grid (NQ/256, 3), block 256. Each block: 256 queries, full 32x512 accumulator across threads.
__global__ void wmean_kernel(const float* __restrict__ qd, const float* __restrict__ qf) {
    __shared__ float s_soft[256][KP];   // 32 KB
    __shared__ float s_qf[8][C];        // 16 KB
    const int step  = blockIdx.y;
    const int qbase = blockIdx.x * 256;
    const int tid   = threadIdx.x;

    {
        const float inv_t = 1.0f / (float)(step + 1);
        const float* row = qd + (size_t)(qbase + tid) * KP;
        float v[KP];
        float m = -1e30f;
#pragma unroll
        for (int i = 0; i < KP; i++) { v[i] = -row[i] * inv_t; m = fmaxf(m, v[i]); }
        float s = 0.f;
#pragma unroll
        for (int i = 0; i < KP; i++) { v[i] = __expf(v[i] - m); s += v[i]; }
        const float inv = 1.0f / s;
#pragma unroll
        for (int i = 0; i < KP; i++) s_soft[tid][i] = v[i] * inv;
    }
    __syncthreads();

    if (tid < KP) {  // partial column sums for wsum
        float s = 0.f;
        for (int q = 0; q < 256; q++) s += s_soft[q][tid];
        atomicAdd(&g_wsum[step * KP + tid], s);
    }

    const int kg = tid >> 6;    // 0..3  -> 8 k's
    const int cg = tid & 63;    // 0..63 -> 8 c's
    float acc[64];
#pragma unroll
    for (int i = 0; i < 64; i++) acc[i] = 0.f;

    for (int qc = 0; qc < 32; ++qc) {
        __syncthreads();
        const float4* src = (const float4*)(qf + (size_t)(qbase + qc * 8) * C);
        float4* dst = (float4*)&s_qf[0][0];
#pragma unroll
        for (int r = 0; r < 4; r++) dst[tid + 256 * r] = src[tid + 256 * r];
        __syncthreads();
#pragma unroll
        for (int qq = 0; qq < 8; ++qq) {
            const int q = qc * 8 + qq;
            float4 s0 = *(const float4*)&s_soft[q][kg * 8];
            float4 s1 = *(const float4*)&s_soft[q][kg * 8 + 4];
            float4 f0 = *(const float4*)&s_qf[qq][cg * 8];
            float4 f1 = *(const float4*)&s_qf[qq][cg * 8 + 4];
            float sv[8] = {s0.x, s0.y, s0.z, s0.w, s1.x, s1.y, s1.z, s1.w};
            float fv[8] = {f0.x, f0.y, f0.z, f0.w, f1.x, f1.y, f1.z, f1.w};
#pragma unroll
            for (int a = 0; a < 8; a++)
#pragma unroll
                for (int b = 0; b < 8; b++)
                    acc[a * 8 + b] = fmaf(sv[a], fv[b], acc[a * 8 + b]);
        }
    }
    float* base = g_wmean + (size_t)(step * KP + kg * 8) * C + cg * 8;
#pragma unroll
    for (int a = 0; a < 8; a++)
#pragma unroll
        for (int b = 0; b < 8; b++)
            atomicAdd(base + a * C + b, acc[a * 8 + b]);
}

// ---------------- wmean finalize: divide by max(wsum, 1e-6) ----------------
__global__ void wmean_fin_kernel() {
    int idx = blockIdx.x * blockDim.x + threadIdx.x;   // 49152
    if (idx < NSTEPS * KP * C) {
        float w = fmaxf(g_wsum[idx / C], 1e-6f);
        g_wmean[idx] = g_wmean[idx] / w;
    }
}

// ============ split-K tiny-GEMM template pattern: 32-row A in smem, acc[32]/thread ============

// MLP layer 1: g_h[step] += concat(refined, wmean[step]) @ W1   (K=1024 split into 16x64)
// grid (HREF/64, 1024/64) = (8,16), block 256 = (64 n, 4 kp)
__global__ void gemm1_kernel(const float* __restrict__ refined, const float* __restrict__ W1,
                             int step) {
    __shared__ float a_s[64][KP];        // [ii][k], 8 KB
    __shared__ float red[4][KP][64];     // 32 KB
    const int tid = threadIdx.x;
    const int n  = tid & 63;
    const int kp = tid >> 6;
    const int ng = blockIdx.x * 64 + n;
    const int kbase = blockIdx.y * 64;

#pragma unroll
    for (int r = 0; r < 8; r++) {
        int idx = tid + 256 * r;         // 0..2047
        int ii = idx >> 5, k = idx & 31;
        int i = kbase + ii;
        a_s[ii][k] = (i < C) ? refined[k * C + i]
                             : g_wmean[(size_t)(step * KP + k) * C + (i - C)];
    }
    __syncthreads();

    float acc[KP];
#pragma unroll
    for (int k = 0; k < KP; k++) acc[k] = 0.f;

    const float* wptr = W1 + (size_t)(kbase + kp * 16) * HREF + ng;
#pragma unroll
    for (int ii = 0; ii < 16; ii++) {
        const float w = wptr[(size_t)ii * HREF];
        const float4* av = (const float4*)&a_s[kp * 16 + ii][0];
#pragma unroll
        for (int k4 = 0; k4 < 8; k4++) {
            float4 a4 = av[k4];
            acc[k4 * 4 + 0] = fmaf(a4.x, w, acc[k4 * 4 + 0]);
            acc[k4 * 4 + 1] = fmaf(a4.y, w, acc[k4 * 4 + 1]);
            acc[k4 * 4 + 2] = fmaf(a4.z, w, acc[k4 * 4 + 2]);
            acc[k4 * 4 + 3] = fmaf(a4.w, w, acc[k4 * 4 + 3]);
        }
    }
#pragma unroll
    for (int k = 0; k < KP; k++) red[kp][k][n] = acc[k];
    __syncthreads();
    if (tid < 64) {
#pragma unroll
        for (int k = 0; k < KP; k++) {
            float s = red[0][k][n] + red[1][k][n] + red[2][k][n] + red[3][k][n];
            atomicAdd(&g_h[(size_t)(step * KP + k) * HREF + ng], s);
        }
    }
}

// MLP layer 2: refined += 0.1*(relu(g_h[step]+b1) @ W2 + b2)   (J=512 split into 16x32)
// grid (C/64, 512/32) = (8,16), block 256 = (64 n, 4 kp of 8 j each)
__global__ void gemm2_kernel(float* __restrict__ refined, const float* __restrict__ W2,
                             const float* __restrict__ b1, const float* __restrict__ b2,
                             int step) {
    __shared__ float a_s[32][KP];        // [ii][k], 4 KB
    __shared__ float red[4][KP][64];     // 32 KB
    const int tid = threadIdx.x;
    const int n  = tid & 63;
    const int kp = tid >> 6;
    const int cg = blockIdx.x * 64 + n;
    const int jbase = blockIdx.y * 32;

#pragma unroll
    for (int r = 0; r < 4; r++) {
        int idx = tid + 256 * r;         // 0..1023
        int ii = idx >> 5, k = idx & 31;
        int j = jbase + ii;
        a_s[ii][k] = fmaxf(g_h[(size_t)(step * KP + k) * HREF + j] + b1[j], 0.f);
    }
    __syncthreads();

    float acc[KP];
#pragma unroll
    for (int k = 0; k < KP; k++) acc[k] = 0.f;

    const float* wptr = W2 + (size_t)(jbase + kp * 8) * C + cg;
#pragma unroll
    for (int ii = 0; ii < 8; ii++) {
        const float w = wptr[(size_t)ii * C];
        const float4* av = (const float4*)&a_s[kp * 8 + ii][0];
#pragma unroll
        for (int k4 = 0; k4 < 8; k4++) {
            float4 a4 = av[k4];
            acc[k4 * 4 + 0] = fmaf(a4.x, w, acc[k4 * 4 + 0]);
            acc[k4 * 4 + 1] = fmaf(a4.y, w, acc[k4 * 4 + 1]);
            acc[k4 * 4 + 2] = fmaf(a4.z, w, acc[k4 * 4 + 2]);
            acc[k4 * 4 + 3] = fmaf(a4.w, w, acc[k4 * 4 + 3]);
        }
    }
#pragma unroll
    for (int k = 0; k < KP; k++) red[kp][k][n] = acc[k];
    __syncthreads();
    if (tid < 64) {
        const float b2v = (blockIdx.y == 0) ? b2[cg] : 0.f;
#pragma unroll
        for (int k = 0; k < KP; k++) {
            float s = red[0][k][n] + red[1][k][n] + red[2][k][n] + red[3][k][n];
            atomicAdd(&refined[k * C + cg], 0.1f * (s + b2v));
        }
    }
}

// hp = prototypes @ Wc1[:C]   (C=512 split into 16x32)
// grid (HCONF/64, 512/32) = (4,16), block 256
__global__ void hp_kernel(const float* __restrict__ proto, const float* __restrict__ Wc1) {
    __shared__ float a_s[32][KP];
    __shared__ float red[4][KP][64];
    const int tid = threadIdx.x;
    const int n  = tid & 63;
    const int kp = tid >> 6;
    const int ng = blockIdx.x * 64 + n;
    const int cbase = blockIdx.y * 32;

#pragma unroll
    for (int r = 0; r < 4; r++) {
        int idx = tid + 256 * r;
        int ii = idx >> 5, k = idx & 31;
        a_s[ii][k] = proto[k * C + cbase + ii];
    }
    __syncthreads();

    float acc[KP];
#pragma unroll
    for (int k = 0; k < KP; k++) acc[k] = 0.f;

    const float* wptr = Wc1 + (size_t)(cbase + kp * 8) * HCONF + ng;
#pragma unroll
    for (int ii = 0; ii < 8; ii++) {
        const float w = wptr[(size_t)ii * HCONF];
        const float4* av = (const float4*)&a_s[kp * 8 + ii][0];
#pragma unroll
        for (int k4 = 0; k4 < 8; k4++) {
            float4 a4 = av[k4];
            acc[k4 * 4 + 0] = fmaf(a4.x, w, acc[k4 * 4 + 0]);
            acc[k4 * 4 + 1] = fmaf(a4.y, w, acc[k4 * 4 + 1]);
            acc[k4 * 4 + 2] = fmaf(a4.z, w, acc[k4 * 4 + 2]);
            acc[k4 * 4 + 3] = fmaf(a4.w, w, acc[k4 * 4 + 3]);
        }
    }
#pragma unroll
    for (int k = 0; k < KP; k++) red[kp][k][n] = acc[k];
    __syncthreads();
    if (tid < 64) {
#pragma unroll
        for (int k = 0; k < KP; k++) {
            float s = red[0][k][n] + red[1][k][n] + red[2][k][n] + red[3][k][n];
            atomicAdd(&g_hp[k * HCONF + ng], s);
        }
    }
}

// ---------------- hq = qf @ Wc1[C:]  (M=16384, N=256, K=512 tiled fp32 GEMM) ----------------
__global__ void hq_kernel(const float* __restrict__ qf, const float* __restrict__ Wc1) {
    const float* __restrict__ B = Wc1 + (size_t)C * HCONF;   // Wq, (512 x 256) row-major
    __shared__ float As[16][128];   // 8 KB (k-major)
    __shared__ float Bs[16][64];    // 4 KB

    const int m0 = blockIdx.x * 128;
    const int n0 = blockIdx.y * 64;
    const int tid = threadIdx.x;    // 256
    const int tm = tid & 15;        // 16 m-groups of 8
    const int tn = tid >> 4;        // 16 n-groups of 4

    const int la_m = tid >> 2;          // 0..63
    const int la_k = (tid & 3) * 4;     // 0,4,8,12
    const int lb_c = tid >> 4;          // 0..15
    const int lb_h = (tid & 15) * 4;    // 0..60

    float4 acc[8];
#pragma unroll
    for (int i = 0; i < 8; i++) acc[i] = make_float4(0.f, 0.f, 0.f, 0.f);

    for (int kk = 0; kk < C; kk += 16) {
        __syncthreads();
        float4 a0 = *(const float4*)(qf + (size_t)(m0 + la_m) * C + kk + la_k);
        float4 a1 = *(const float4*)(qf + (size_t)(m0 + la_m + 64) * C + kk + la_k);
        As[la_k + 0][la_m] = a0.x; As[la_k + 1][la_m] = a0.y;
        As[la_k + 2][la_m] = a0.z; As[la_k + 3][la_m] = a0.w;
        As[la_k + 0][la_m + 64] = a1.x; As[la_k + 1][la_m + 64] = a1.y;
        As[la_k + 2][la_m + 64] = a1.z; As[la_k + 3][la_m + 64] = a1.w;
        *(float4*)&Bs[lb_c][lb_h] = *(const float4*)(B + (size_t)(kk + lb_c) * HCONF + n0 + lb_h);
        __syncthreads();
#pragma unroll
        for (int k2 = 0; k2 < 16; k2++) {
            const float4 am0 = *(const float4*)&As[k2][tm * 8];
            const float4 am1 = *(const float4*)&As[k2][tm * 8 + 4];
            const float4 bn  = *(const float4*)&Bs[k2][tn * 4];
            const float am[8] = {am0.x, am0.y, am0.z, am0.w, am1.x, am1.y, am1.z, am1.w};
#pragma unroll
            for (int i = 0; i < 8; i++) {
                acc[i].x = fmaf(am[i], bn.x, acc[i].x);
                acc[i].y = fmaf(am[i], bn.y, acc[i].y);
                acc[i].z = fmaf(am[i], bn.z, acc[i].z);
                acc[i].w = fmaf(am[i], bn.w, acc[i].w);
            }
        }
    }
#pragma unroll
    for (int i = 0; i < 8; i++)
        *(float4*)(g_hq + (size_t)(m0 + tm * 8 + i) * HCONF + n0 + tn * 4) = acc[i];
}

// ---------------- conf: per-(q,k) fused relu-dot + sigmoid, never materializing hidden ----------------
__global__ void conf_kernel(const float* __restrict__ Wc2, const float* __restrict__ bc1,
                            const float* __restrict__ bc2) {
    __shared__ float s_hp[KP][HCONF];    // 32 KB
    __shared__ float s_part[8][KP];
    const int tid  = threadIdx.x;        // 256
    const int lane = tid & 31;
    const int warp = tid >> 5;

    float* hpflat = &s_hp[0][0];
#pragma unroll
    for (int r = 0; r < 32; r++) hpflat[tid + 256 * r] = g_hp[tid + 256 * r];

    float wc2r[8], bcr[8];
#pragma unroll
    for (int j = 0; j < 8; j++) {
        wc2r[j] = Wc2[lane + 32 * j];
        bcr[j]  = bc1[lane + 32 * j];
    }
    const float bc2v = bc2[0];
    __syncthreads();

    float conf_acc = 0.f;
    const int nwarps = gridDim.x * 8;
    for (int q = blockIdx.x * 8 + warp; q < NQ; q += nwarps) {
        float a[8];
#pragma unroll
        for (int j = 0; j < 8; j++) a[j] = g_hq[(size_t)q * HCONF + lane + 32 * j] + bcr[j];
#pragma unroll 4
        for (int k = 0; k < KP; k++) {
            float s = 0.f;
#pragma unroll
            for (int j = 0; j < 8; j++) {
                float t = fmaxf(s_hp[k][lane + 32 * j] + a[j], 0.f);
                s = fmaf(t, wc2r[j], s);
            }
            s += __shfl_xor_sync(0xffffffffu, s, 16);
            s += __shfl_xor_sync(0xffffffffu, s, 8);
            s += __shfl_xor_sync(0xffffffffu, s, 4);
            s += __shfl_xor_sync(0xffffffffu, s, 2);
            s += __shfl_xor_sync(0xffffffffu, s, 1);
            const float sig = 1.0f / (1.0f + __expf(-(s + bc2v)));
            if (k == lane) conf_acc += sig;
        }
    }
    s_part[warp][lane] = conf_acc;
    __syncthreads();
    if (tid < KP) {
        float t = 0.f;
#pragma unroll
        for (int w = 0; w < 8; w++) t += s_part[w][tid];
        atomicAdd(&g_conf[tid], t);
    }
}

// ---------------- final: confidence mean ----------------
__global__ void conf_fin_kernel(float* __restrict__ out) {
    int tid = threadIdx.x;
    if (tid < KP) out[KP * C + tid] = g_conf[tid] * (1.0f / (float)NQ);
}

// ---------------- launch ----------------
extern "C" void kernel_launch(void* const* d_in, const int* in_sizes, int n_in,
                              void* d_out, int out_size) {
    const float* proto = (const float*)d_in[0];
    const float* qf    = (const float*)d_in[1];
    const float* qd    = (const float*)d_in[2];
    const float* W1    = (const float*)d_in[3];
    const float* b1    = (const float*)d_in[4];
    const float* W2    = (const float*)d_in[5];
    const float* b2    = (const float*)d_in[6];
    const float* Wc1   = (const float*)d_in[7];
    const float* bc1   = (const float*)d_in[8];
    const float* Wc2   = (const float*)d_in[9];
    const float* bc2   = (const float*)d_in[10];
    float* out = (float*)d_out;

    init_kernel<<<192, 256>>>(proto, out);
    wmean_kernel<<<dim3(NQ / 256, NSTEPS), 256>>>(qd, qf);
    wmean_fin_kernel<<<192, 256>>>();
    for (int t = 0; t < NSTEPS; t++) {
        gemm1_kernel<<<dim3(HREF / 64, 1024 / 64), 256>>>(out, W1, t);
        gemm2_kernel<<<dim3(C / 64, HREF / 32), 256>>>(out, W2, b1, b2, t);
    }
    hp_kernel<<<dim3(HCONF / 64, C / 32), 256>>>(proto, Wc1);
    hq_kernel<<<dim3(NQ / 128, HCONF / 64), 256>>>(qf, Wc1);
    conf_kernel<<<256, 256>>>(Wc2, bc1, bc2);
    conf_fin_kernel<<<1, 32>>>(out);
}

// round 5
// speedup vs baseline: 2.3240x; 1.3921x over previous
#include <cuda_runtime.h>
#include <mma.h>
#include <cstdint>

using namespace nvcuda;

#define NQ    16384
#define KP    32
#define C     512
#define HREF  512
#define HCONF 256
#define NSTEPS 3

// ---------------- scratch (__device__ globals; no allocation allowed) ----------------
__device__ float g_wmean[NSTEPS * KP * C];
__device__ float g_wsum [NSTEPS * KP];
__device__ float g_h    [NSTEPS * KP * HREF];
__device__ float g_hp   [KP * HCONF];
__device__ float g_hq   [NQ * HCONF];        // 16 MB
__device__ float g_conf [KP];

// ---------------- init ----------------
__global__ void init_kernel(const float* __restrict__ proto, float* __restrict__ out) {
    int idx = blockIdx.x * blockDim.x + threadIdx.x;
    if (idx < NSTEPS * KP * C)    g_wmean[idx] = 0.f;
    if (idx < NSTEPS * KP * HREF) g_h[idx]     = 0.f;
    if (idx < KP * HCONF)         g_hp[idx]    = 0.f;
    if (idx < NSTEPS * KP)        g_wsum[idx]  = 0.f;
    if (idx < KP)                 g_conf[idx]  = 0.f;
    if (idx < KP * C)             out[idx]     = proto[idx];
}

// ---------------- wmean: soft^T @ qf via block-partial outer products (R1 proven) ----------------
__global__ void wmean_kernel(const float* __restrict__ qd, const float* __restrict__ qf) {
    __shared__ float s_soft[256][KP];   // 32 KB
    __shared__ float s_qf[8][C];        // 16 KB
    const int step  = blockIdx.y;
    const int qbase = blockIdx.x * 256;
    const int tid   = threadIdx.x;

    {
        const float inv_t = 1.0f / (float)(step + 1);
        const float* row = qd + (size_t)(qbase + tid) * KP;
        float v[KP];
        float m = -1e30f;
#pragma unroll
        for (int i = 0; i < KP; i++) { v[i] = -row[i] * inv_t; m = fmaxf(m, v[i]); }
        float s = 0.f;
#pragma unroll
        for (int i = 0; i < KP; i++) { v[i] = __expf(v[i] - m); s += v[i]; }
        const float inv = 1.0f / s;
#pragma unroll
        for (int i = 0; i < KP; i++) s_soft[tid][i] = v[i] * inv;
    }
    __syncthreads();

    if (tid < KP) {
        float s = 0.f;
        for (int q = 0; q < 256; q++) s += s_soft[q][tid];
        atomicAdd(&g_wsum[step * KP + tid], s);
    }

    const int kg = tid >> 6;
    const int cg = tid & 63;
    float acc[64];
#pragma unroll
    for (int i = 0; i < 64; i++) acc[i] = 0.f;

    for (int qc = 0; qc < 32; ++qc) {
        __syncthreads();
        const float4* src = (const float4*)(qf + (size_t)(qbase + qc * 8) * C);
        float4* dst = (float4*)&s_qf[0][0];
#pragma unroll
        for (int r = 0; r < 4; r++) dst[tid + 256 * r] = src[tid + 256 * r];
        __syncthreads();
#pragma unroll
        for (int qq = 0; qq < 8; ++qq) {
            const int q = qc * 8 + qq;
            float4 s0 = *(const float4*)&s_soft[q][kg * 8];
            float4 s1 = *(const float4*)&s_soft[q][kg * 8 + 4];
            float4 f0 = *(const float4*)&s_qf[qq][cg * 8];
            float4 f1 = *(const float4*)&s_qf[qq][cg * 8 + 4];
            float sv[8] = {s0.x, s0.y, s0.z, s0.w, s1.x, s1.y, s1.z, s1.w};
            float fv[8] = {f0.x, f0.y, f0.z, f0.w, f1.x, f1.y, f1.z, f1.w};
#pragma unroll
            for (int a = 0; a < 8; a++)
#pragma unroll
                for (int b = 0; b < 8; b++)
                    acc[a * 8 + b] = fmaf(sv[a], fv[b], acc[a * 8 + b]);
        }
    }
    float* base = g_wmean + (size_t)(step * KP + kg * 8) * C + cg * 8;
#pragma unroll
    for (int a = 0; a < 8; a++)
#pragma unroll
        for (int b = 0; b < 8; b++)
            atomicAdd(base + a * C + b, acc[a * 8 + b]);
}

__global__ void wmean_fin_kernel() {
    int idx = blockIdx.x * blockDim.x + threadIdx.x;
    if (idx < NSTEPS * KP * C) {
        float w = fmaxf(g_wsum[idx / C], 1e-6f);
        g_wmean[idx] = g_wmean[idx] / w;
    }
}

// ============ split-K tiny GEMMs (R1 proven) ============
__global__ void gemm1_kernel(const float* __restrict__ refined, const float* __restrict__ W1,
                             int step) {
    __shared__ float a_s[64][KP];
    __shared__ float red[4][KP][64];
    const int tid = threadIdx.x;
    const int n  = tid & 63;
    const int kp = tid >> 6;
    const int ng = blockIdx.x * 64 + n;
    const int kbase = blockIdx.y * 64;

#pragma unroll
    for (int r = 0; r < 8; r++) {
        int idx = tid + 256 * r;
        int ii = idx >> 5, k = idx & 31;
        int i = kbase + ii;
        a_s[ii][k] = (i < C) ? refined[k * C + i]
                             : g_wmean[(size_t)(step * KP + k) * C + (i - C)];
    }
    __syncthreads();

    float acc[KP];
#pragma unroll
    for (int k = 0; k < KP; k++) acc[k] = 0.f;

    const float* wptr = W1 + (size_t)(kbase + kp * 16) * HREF + ng;
#pragma unroll
    for (int ii = 0; ii < 16; ii++) {
        const float w = wptr[(size_t)ii * HREF];
        const float4* av = (const float4*)&a_s[kp * 16 + ii][0];
#pragma unroll
        for (int k4 = 0; k4 < 8; k4++) {
            float4 a4 = av[k4];
            acc[k4 * 4 + 0] = fmaf(a4.x, w, acc[k4 * 4 + 0]);
            acc[k4 * 4 + 1] = fmaf(a4.y, w, acc[k4 * 4 + 1]);
            acc[k4 * 4 + 2] = fmaf(a4.z, w, acc[k4 * 4 + 2]);
            acc[k4 * 4 + 3] = fmaf(a4.w, w, acc[k4 * 4 + 3]);
        }
    }
#pragma unroll
    for (int k = 0; k < KP; k++) red[kp][k][n] = acc[k];
    __syncthreads();
    if (tid < 64) {
#pragma unroll
        for (int k = 0; k < KP; k++) {
            float s = red[0][k][n] + red[1][k][n] + red[2][k][n] + red[3][k][n];
            atomicAdd(&g_h[(size_t)(step * KP + k) * HREF + ng], s);
        }
    }
}

__global__ void gemm2_kernel(float* __restrict__ refined, const float* __restrict__ W2,
                             const float* __restrict__ b1, const float* __restrict__ b2,
                             int step) {
    __shared__ float a_s[32][KP];
    __shared__ float red[4][KP][64];
    const int tid = threadIdx.x;
    const int n  = tid & 63;
    const int kp = tid >> 6;
    const int cg = blockIdx.x * 64 + n;
    const int jbase = blockIdx.y * 32;

#pragma unroll
    for (int r = 0; r < 4; r++) {
        int idx = tid + 256 * r;
        int ii = idx >> 5, k = idx & 31;
        int j = jbase + ii;
        a_s[ii][k] = fmaxf(g_h[(size_t)(step * KP + k) * HREF + j] + b1[j], 0.f);
    }
    __syncthreads();

    float acc[KP];
#pragma unroll
    for (int k = 0; k < KP; k++) acc[k] = 0.f;

    const float* wptr = W2 + (size_t)(jbase + kp * 8) * C + cg;
#pragma unroll
    for (int ii = 0; ii < 8; ii++) {
        const float w = wptr[(size_t)ii * C];
        const float4* av = (const float4*)&a_s[kp * 8 + ii][0];
#pragma unroll
        for (int k4 = 0; k4 < 8; k4++) {
            float4 a4 = av[k4];
            acc[k4 * 4 + 0] = fmaf(a4.x, w, acc[k4 * 4 + 0]);
            acc[k4 * 4 + 1] = fmaf(a4.y, w, acc[k4 * 4 + 1]);
            acc[k4 * 4 + 2] = fmaf(a4.z, w, acc[k4 * 4 + 2]);
            acc[k4 * 4 + 3] = fmaf(a4.w, w, acc[k4 * 4 + 3]);
        }
    }
#pragma unroll
    for (int k = 0; k < KP; k++) red[kp][k][n] = acc[k];
    __syncthreads();
    if (tid < 64) {
        const float b2v = (blockIdx.y == 0) ? b2[cg] : 0.f;
#pragma unroll
        for (int k = 0; k < KP; k++) {
            float s = red[0][k][n] + red[1][k][n] + red[2][k][n] + red[3][k][n];
            atomicAdd(&refined[k * C + cg], 0.1f * (s + b2v));
        }
    }
}

__global__ void hp_kernel(const float* __restrict__ proto, const float* __restrict__ Wc1) {
    __shared__ float a_s[32][KP];
    __shared__ float red[4][KP][64];
    const int tid = threadIdx.x;
    const int n  = tid & 63;
    const int kp = tid >> 6;
    const int ng = blockIdx.x * 64 + n;
    const int cbase = blockIdx.y * 32;

#pragma unroll
    for (int r = 0; r < 4; r++) {
        int idx = tid + 256 * r;
        int ii = idx >> 5, k = idx & 31;
        a_s[ii][k] = proto[k * C + cbase + ii];
    }
    __syncthreads();

    float acc[KP];
#pragma unroll
    for (int k = 0; k < KP; k++) acc[k] = 0.f;

    const float* wptr = Wc1 + (size_t)(cbase + kp * 8) * HCONF + ng;
#pragma unroll
    for (int ii = 0; ii < 8; ii++) {
        const float w = wptr[(size_t)ii * HCONF];
        const float4* av = (const float4*)&a_s[kp * 8 + ii][0];
#pragma unroll
        for (int k4 = 0; k4 < 8; k4++) {
            float4 a4 = av[k4];
            acc[k4 * 4 + 0] = fmaf(a4.x, w, acc[k4 * 4 + 0]);
            acc[k4 * 4 + 1] = fmaf(a4.y, w, acc[k4 * 4 + 1]);
            acc[k4 * 4 + 2] = fmaf(a4.z, w, acc[k4 * 4 + 2]);
            acc[k4 * 4 + 3] = fmaf(a4.w, w, acc[k4 * 4 + 3]);
        }
    }
#pragma unroll
    for (int k = 0; k < KP; k++) red[kp][k][n] = acc[k];
    __syncthreads();
    if (tid < 64) {
#pragma unroll
        for (int k = 0; k < KP; k++) {
            float s = red[0][k][n] + red[1][k][n] + red[2][k][n] + red[3][k][n];
            atomicAdd(&g_hp[k * HCONF + ng], s);
        }
    }
}

// ---------------- hq = qf @ Wq via WMMA tf32 (m16n16k8, base ISA) ----------------
// grid (NQ/128, HCONF/64), block 256 (8 warps, 4x2). CTA tile 128x64, warp tile 32x32.
#define A_LD 36
#define B_LD 68
__global__ void __launch_bounds__(256) hq_kernel(const float* __restrict__ qf,
                                                 const float* __restrict__ Wc1) {
    const float* __restrict__ B = Wc1 + (size_t)C * HCONF;   // Wq [512][256] row-major
    __shared__ float As[128][A_LD];   // 18432 B
    __shared__ float Bs[32][B_LD];    //  8704 B

    const int tid = threadIdx.x;
    const int wid = tid >> 5;
    const int wm = wid >> 1;          // 0..3 -> m offset wm*32
    const int wn = wid & 1;           // 0..1 -> n offset wn*32
    const int m0 = blockIdx.x * 128;
    const int n0 = blockIdx.y * 64;

    wmma::fragment<wmma::accumulator, 16, 16, 8, float> acc[2][2];
#pragma unroll
    for (int mi = 0; mi < 2; mi++)
#pragma unroll
        for (int ni = 0; ni < 2; ni++) wmma::fill_fragment(acc[mi][ni], 0.f);

    for (int kk = 0; kk < C; kk += 32) {
        __syncthreads();
        // load A tile 128x32 (1024 float4, 4/thread)
#pragma unroll
        for (int i = 0; i < 4; i++) {
            int f = tid + 256 * i; int row = f >> 3; int c4 = f & 7;
            *(float4*)&As[row][c4 * 4] = *(const float4*)(qf + (size_t)(m0 + row) * C + kk + c4 * 4);
        }
        // load B tile 32x64 (512 float4, 2/thread)
#pragma unroll
        for (int i = 0; i < 2; i++) {
            int f = tid + 256 * i; int row = f >> 4; int c4 = f & 15;
            *(float4*)&Bs[row][c4 * 4] = *(const float4*)(B + (size_t)(kk + row) * HCONF + n0 + c4 * 4);
        }
        __syncthreads();

#pragma unroll
        for (int s = 0; s < 4; s++) {
            wmma::fragment<wmma::matrix_a, 16, 16, 8, wmma::precision::tf32, wmma::row_major> af[2];
            wmma::fragment<wmma::matrix_b, 16, 16, 8, wmma::precision::tf32, wmma::row_major> bf[2];
#pragma unroll
            for (int mi = 0; mi < 2; mi++) {
                wmma::load_matrix_sync(af[mi], &As[wm * 32 + mi * 16][s * 8], A_LD);
#pragma unroll
                for (int t = 0; t < af[mi].num_elements; t++)
                    af[mi].x[t] = wmma::__float_to_tf32(af[mi].x[t]);
            }
#pragma unroll
            for (int ni = 0; ni < 2; ni++) {
                wmma::load_matrix_sync(bf[ni], &Bs[s * 8][wn * 32 + ni * 16], B_LD);
#pragma unroll
                for (int t = 0; t < bf[ni].num_elements; t++)
                    bf[ni].x[t] = wmma::__float_to_tf32(bf[ni].x[t]);
            }
#pragma unroll
            for (int mi = 0; mi < 2; mi++)
#pragma unroll
                for (int ni = 0; ni < 2; ni++)
                    wmma::mma_sync(acc[mi][ni], af[mi], bf[ni], acc[mi][ni]);
        }
    }

#pragma unroll
    for (int mi = 0; mi < 2; mi++)
#pragma unroll
        for (int ni = 0; ni < 2; ni++)
            wmma::store_matrix_sync(
                g_hq + (size_t)(m0 + wm * 32 + mi * 16) * HCONF + n0 + wn * 32 + ni * 16,
                acc[mi][ni], HCONF, wmma::mem_row_major);
}

// ---------------- conf (R1 proven) ----------------
__global__ void conf_kernel(const float* __restrict__ Wc2, const float* __restrict__ bc1,
                            const float* __restrict__ bc2) {
    __shared__ float s_hp[KP][HCONF];
    __shared__ float s_part[8][KP];
    const int tid  = threadIdx.x;
    const int lane = tid & 31;
    const int warp = tid >> 5;

    float* hpflat = &s_hp[0][0];
#pragma unroll
    for (int r = 0; r < 32; r++) hpflat[tid + 256 * r] = g_hp[tid + 256 * r];

    float wc2r[8], bcr[8];
#pragma unroll
    for (int j = 0; j < 8; j++) {
        wc2r[j] = Wc2[lane + 32 * j];
        bcr[j]  = bc1[lane + 32 * j];
    }
    const float bc2v = bc2[0];
    __syncthreads();

    float conf_acc = 0.f;
    const int nwarps = gridDim.x * 8;
    for (int q = blockIdx.x * 8 + warp; q < NQ; q += nwarps) {
        float a[8];
#pragma unroll
        for (int j = 0; j < 8; j++) a[j] = g_hq[(size_t)q * HCONF + lane + 32 * j] + bcr[j];
#pragma unroll 4
        for (int k = 0; k < KP; k++) {
            float s = 0.f;
#pragma unroll
            for (int j = 0; j < 8; j++) {
                float t = fmaxf(s_hp[k][lane + 32 * j] + a[j], 0.f);
                s = fmaf(t, wc2r[j], s);
            }
            s += __shfl_xor_sync(0xffffffffu, s, 16);
            s += __shfl_xor_sync(0xffffffffu, s, 8);
            s += __shfl_xor_sync(0xffffffffu, s, 4);
            s += __shfl_xor_sync(0xffffffffu, s, 2);
            s += __shfl_xor_sync(0xffffffffu, s, 1);
            const float sig = 1.0f / (1.0f + __expf(-(s + bc2v)));
            if (k == lane) conf_acc += sig;
        }
    }
    s_part[warp][lane] = conf_acc;
    __syncthreads();
    if (tid < KP) {
        float t = 0.f;
#pragma unroll
        for (int w = 0; w < 8; w++) t += s_part[w][tid];
        atomicAdd(&g_conf[tid], t);
    }
}

__global__ void conf_fin_kernel(float* __restrict__ out) {
    int tid = threadIdx.x;
    if (tid < KP) out[KP * C + tid] = g_conf[tid] * (1.0f / (float)NQ);
}

// ---------------- launch ----------------
extern "C" void kernel_launch(void* const* d_in, const int* in_sizes, int n_in,
                              void* d_out, int out_size) {
    const float* proto = (const float*)d_in[0];
    const float* qf    = (const float*)d_in[1];
    const float* qd    = (const float*)d_in[2];
    const float* W1    = (const float*)d_in[3];
    const float* b1    = (const float*)d_in[4];
    const float* W2    = (const float*)d_in[5];
    const float* b2    = (const float*)d_in[6];
    const float* Wc1   = (const float*)d_in[7];
    const float* bc1   = (const float*)d_in[8];
    const float* Wc2   = (const float*)d_in[9];
    const float* bc2   = (const float*)d_in[10];
    float* out = (float*)d_out;

    init_kernel<<<192, 256>>>(proto, out);
    wmean_kernel<<<dim3(NQ / 256, NSTEPS), 256>>>(qd, qf);
    wmean_fin_kernel<<<192, 256>>>();
    for (int t = 0; t < NSTEPS; t++) {
        gemm1_kernel<<<dim3(HREF / 64, 1024 / 64), 256>>>(out, W1, t);
        gemm2_kernel<<<dim3(C / 64, HREF / 32), 256>>>(out, W2, b1, b2, t);
    }
    hp_kernel<<<dim3(HCONF / 64, C / 32), 256>>>(proto, Wc1);
    hq_kernel<<<dim3(NQ / 128, HCONF / 64), 256>>>(qf, Wc1);
    conf_kernel<<<256, 256>>>(Wc2, bc1, bc2);
    conf_fin_kernel<<<1, 32>>>(out);
}

// round 6
// speedup vs baseline: 2.6910x; 1.1579x over previous
#include <cuda_runtime.h>
#include <mma.h>
#include <cstdint>

using namespace nvcuda;

#define NQ    16384
#define KP    32
#define C     512
#define HREF  512
#define HCONF 256
#define NSTEPS 3

// ---------------- scratch (__device__ globals; no allocation allowed) ----------------
__device__ float g_wmean[NSTEPS * KP * C];
__device__ float g_wsum [NSTEPS * KP];
__device__ float g_h    [NSTEPS * KP * HREF];
__device__ float g_hp   [KP * HCONF];
__device__ float g_hq   [NQ * HCONF];        // 16 MB
__device__ float g_conf [KP];

// ---------------- init ----------------
__global__ void init_kernel(const float* __restrict__ proto, float* __restrict__ out) {
    int idx = blockIdx.x * blockDim.x + threadIdx.x;
    if (idx < NSTEPS * KP * C)    g_wmean[idx] = 0.f;
    if (idx < NSTEPS * KP * HREF) g_h[idx]     = 0.f;
    if (idx < KP * HCONF)         g_hp[idx]    = 0.f;
    if (idx < NSTEPS * KP)        g_wsum[idx]  = 0.f;
    if (idx < KP)                 g_conf[idx]  = 0.f;
    if (idx < KP * C)             out[idx]     = proto[idx];
}

// ---------------- wmean via WMMA tf32: soft^T @ qf ----------------
// grid (NQ/256, 3), block 256 (8 warps). Per block: 256 queries, output 32x512 partial.
// dyn smem: s_soft[256][40] (40960 B) + s_out[32][512] (65536 B) = 106496 B
#define SOFT_LD 40
__global__ void __launch_bounds__(256) wmean_tc_kernel(const float* __restrict__ qd,
                                                       const float* __restrict__ qf) {
    extern __shared__ float sm[];
    float (*s_soft)[SOFT_LD] = (float(*)[SOFT_LD])sm;
    float (*s_out)[C]        = (float(*)[C])(sm + 256 * SOFT_LD);

    const int step  = blockIdx.y;
    const int qbase = blockIdx.x * 256;
    const int tid   = threadIdx.x;
    const int wid   = tid >> 5;

    {   // softmax for this thread's query
        const float inv_t = 1.0f / (float)(step + 1);
        const float* row = qd + (size_t)(qbase + tid) * KP;
        float v[KP];
        float m = -1e30f;
#pragma unroll
        for (int i = 0; i < KP; i++) { v[i] = -row[i] * inv_t; m = fmaxf(m, v[i]); }
        float s = 0.f;
#pragma unroll
        for (int i = 0; i < KP; i++) { v[i] = __expf(v[i] - m); s += v[i]; }
        const float inv = 1.0f / s;
#pragma unroll
        for (int i = 0; i < KP; i++) s_soft[tid][i] = v[i] * inv;
    }
    __syncthreads();

    if (tid < KP) {   // partial column sums for wsum
        float s = 0.f;
        for (int q = 0; q < 256; q++) s += s_soft[q][tid];
        atomicAdd(&g_wsum[step * KP + tid], s);
    }

    // tensor phase: each warp owns n-slice [wid*64, wid*64+64)
    const int n0 = wid * 64;
    wmma::fragment<wmma::accumulator, 16, 16, 8, float> acc[2][4];
#pragma unroll
    for (int mi = 0; mi < 2; mi++)
#pragma unroll
        for (int ni = 0; ni < 4; ni++) wmma::fill_fragment(acc[mi][ni], 0.f);

    for (int kq = 0; kq < 256; kq += 8) {
        wmma::fragment<wmma::matrix_a, 16, 16, 8, wmma::precision::tf32, wmma::col_major> af[2];
        wmma::fragment<wmma::matrix_b, 16, 16, 8, wmma::precision::tf32, wmma::row_major> bf[4];
#pragma unroll
        for (int mi = 0; mi < 2; mi++) {
            wmma::load_matrix_sync(af[mi], &s_soft[kq][mi * 16], SOFT_LD);
#pragma unroll
            for (int t = 0; t < af[mi].num_elements; t++)
                af[mi].x[t] = wmma::__float_to_tf32(af[mi].x[t]);
        }
#pragma unroll
        for (int ni = 0; ni < 4; ni++) {
            wmma::load_matrix_sync(bf[ni], qf + (size_t)(qbase + kq) * C + n0 + ni * 16, C);
#pragma unroll
            for (int t = 0; t < bf[ni].num_elements; t++)
                bf[ni].x[t] = wmma::__float_to_tf32(bf[ni].x[t]);
        }
#pragma unroll
        for (int mi = 0; mi < 2; mi++)
#pragma unroll
            for (int ni = 0; ni < 4; ni++)
                wmma::mma_sync(acc[mi][ni], af[mi], bf[ni], acc[mi][ni]);
    }

#pragma unroll
    for (int mi = 0; mi < 2; mi++)
#pragma unroll
        for (int ni = 0; ni < 4; ni++)
            wmma::store_matrix_sync(&s_out[mi * 16][n0 + ni * 16], acc[mi][ni], C,
                                    wmma::mem_row_major);
    __syncthreads();

    float* base = g_wmean + (size_t)step * KP * C;
    const float* src = &s_out[0][0];
#pragma unroll
    for (int i = 0; i < 64; i++) {
        int idx = tid + 256 * i;          // 0..16383 == m*512 + c
        atomicAdd(base + idx, src[idx]);
    }
}

__global__ void wmean_fin_kernel() {
    int idx = blockIdx.x * blockDim.x + threadIdx.x;
    if (idx < NSTEPS * KP * C) {
        float w = fmaxf(g_wsum[idx / C], 1e-6f);
        g_wmean[idx] = g_wmean[idx] / w;
    }
}

// ============ split-K tiny GEMMs (prefetched weight columns) ============
__global__ void gemm1_kernel(const float* __restrict__ refined, const float* __restrict__ W1,
                             int step) {
    __shared__ float a_s[64][KP];
    __shared__ float red[4][KP][64];
    const int tid = threadIdx.x;
    const int n  = tid & 63;
    const int kp = tid >> 6;
    const int ng = blockIdx.x * 64 + n;
    const int kbase = blockIdx.y * 64;

#pragma unroll
    for (int r = 0; r < 8; r++) {
        int idx = tid + 256 * r;
        int ii = idx >> 5, k = idx & 31;
        int i = kbase + ii;
        a_s[ii][k] = (i < C) ? refined[k * C + i]
                             : g_wmean[(size_t)(step * KP + k) * C + (i - C)];
    }
    __syncthreads();

    float acc[KP];
#pragma unroll
    for (int k = 0; k < KP; k++) acc[k] = 0.f;

    const float* wptr = W1 + (size_t)(kbase + kp * 16) * HREF + ng;
    float wv[16];
#pragma unroll
    for (int ii = 0; ii < 16; ii++) wv[ii] = wptr[(size_t)ii * HREF];

#pragma unroll
    for (int ii = 0; ii < 16; ii++) {
        const float w = wv[ii];
        const float4* av = (const float4*)&a_s[kp * 16 + ii][0];
#pragma unroll
        for (int k4 = 0; k4 < 8; k4++) {
            float4 a4 = av[k4];
            acc[k4 * 4 + 0] = fmaf(a4.x, w, acc[k4 * 4 + 0]);
            acc[k4 * 4 + 1] = fmaf(a4.y, w, acc[k4 * 4 + 1]);
            acc[k4 * 4 + 2] = fmaf(a4.z, w, acc[k4 * 4 + 2]);
            acc[k4 * 4 + 3] = fmaf(a4.w, w, acc[k4 * 4 + 3]);
        }
    }
#pragma unroll
    for (int k = 0; k < KP; k++) red[kp][k][n] = acc[k];
    __syncthreads();
    if (tid < 64) {
#pragma unroll
        for (int k = 0; k < KP; k++) {
            float s = red[0][k][n] + red[1][k][n] + red[2][k][n] + red[3][k][n];
            atomicAdd(&g_h[(size_t)(step * KP + k) * HREF + ng], s);
        }
    }
}

__global__ void gemm2_kernel(float* __restrict__ refined, const float* __restrict__ W2,
                             const float* __restrict__ b1, const float* __restrict__ b2,
                             int step) {
    __shared__ float a_s[32][KP];
    __shared__ float red[4][KP][64];
    const int tid = threadIdx.x;
    const int n  = tid & 63;
    const int kp = tid >> 6;
    const int cg = blockIdx.x * 64 + n;
    const int jbase = blockIdx.y * 32;

#pragma unroll
    for (int r = 0; r < 4; r++) {
        int idx = tid + 256 * r;
        int ii = idx >> 5, k = idx & 31;
        int j = jbase + ii;
        a_s[ii][k] = fmaxf(g_h[(size_t)(step * KP + k) * HREF + j] + b1[j], 0.f);
    }
    __syncthreads();

    float acc[KP];
#pragma unroll
    for (int k = 0; k < KP; k++) acc[k] = 0.f;

    const float* wptr = W2 + (size_t)(jbase + kp * 8) * C + cg;
    float wv[8];
#pragma unroll
    for (int ii = 0; ii < 8; ii++) wv[ii] = wptr[(size_t)ii * C];

#pragma unroll
    for (int ii = 0; ii < 8; ii++) {
        const float w = wv[ii];
        const float4* av = (const float4*)&a_s[kp * 8 + ii][0];
#pragma unroll
        for (int k4 = 0; k4 < 8; k4++) {
            float4 a4 = av[k4];
            acc[k4 * 4 + 0] = fmaf(a4.x, w, acc[k4 * 4 + 0]);
            acc[k4 * 4 + 1] = fmaf(a4.y, w, acc[k4 * 4 + 1]);
            acc[k4 * 4 + 2] = fmaf(a4.z, w, acc[k4 * 4 + 2]);
            acc[k4 * 4 + 3] = fmaf(a4.w, w, acc[k4 * 4 + 3]);
        }
    }
#pragma unroll
    for (int k = 0; k < KP; k++) red[kp][k][n] = acc[k];
    __syncthreads();
    if (tid < 64) {
        const float b2v = (blockIdx.y == 0) ? b2[cg] : 0.f;
#pragma unroll
        for (int k = 0; k < KP; k++) {
            float s = red[0][k][n] + red[1][k][n] + red[2][k][n] + red[3][k][n];
            atomicAdd(&refined[k * C + cg], 0.1f * (s + b2v));
        }
    }
}

__global__ void hp_kernel(const float* __restrict__ proto, const float* __restrict__ Wc1) {
    __shared__ float a_s[32][KP];
    __shared__ float red[4][KP][64];
    const int tid = threadIdx.x;
    const int n  = tid & 63;
    const int kp = tid >> 6;
    const int ng = blockIdx.x * 64 + n;
    const int cbase = blockIdx.y * 32;

#pragma unroll
    for (int r = 0; r < 4; r++) {
        int idx = tid + 256 * r;
        int ii = idx >> 5, k = idx & 31;
        a_s[ii][k] = proto[k * C + cbase + ii];
    }
    __syncthreads();

    float acc[KP];
#pragma unroll
    for (int k = 0; k < KP; k++) acc[k] = 0.f;

    const float* wptr = Wc1 + (size_t)(cbase + kp * 8) * HCONF + ng;
    float wv[8];
#pragma unroll
    for (int ii = 0; ii < 8; ii++) wv[ii] = wptr[(size_t)ii * HCONF];

#pragma unroll
    for (int ii = 0; ii < 8; ii++) {
        const float w = wv[ii];
        const float4* av = (const float4*)&a_s[kp * 8 + ii][0];
#pragma unroll
        for (int k4 = 0; k4 < 8; k4++) {
            float4 a4 = av[k4];
            acc[k4 * 4 + 0] = fmaf(a4.x, w, acc[k4 * 4 + 0]);
            acc[k4 * 4 + 1] = fmaf(a4.y, w, acc[k4 * 4 + 1]);
            acc[k4 * 4 + 2] = fmaf(a4.z, w, acc[k4 * 4 + 2]);
            acc[k4 * 4 + 3] = fmaf(a4.w, w, acc[k4 * 4 + 3]);
        }
    }
#pragma unroll
    for (int k = 0; k < KP; k++) red[kp][k][n] = acc[k];
    __syncthreads();
    if (tid < 64) {
#pragma unroll
        for (int k = 0; k < KP; k++) {
            float s = red[0][k][n] + red[1][k][n] + red[2][k][n] + red[3][k][n];
            atomicAdd(&g_hp[k * HCONF + ng], s);
        }
    }
}

// ---------------- hq = qf @ Wq via WMMA tf32 (R5 proven) ----------------
#define A_LD 36
#define B_LD 68
__global__ void __launch_bounds__(256) hq_kernel(const float* __restrict__ qf,
                                                 const float* __restrict__ Wc1) {
    const float* __restrict__ B = Wc1 + (size_t)C * HCONF;   // Wq [512][256] row-major
    __shared__ float As[128][A_LD];
    __shared__ float Bs[32][B_LD];

    const int tid = threadIdx.x;
    const int wid = tid >> 5;
    const int wm = wid >> 1;
    const int wn = wid & 1;
    const int m0 = blockIdx.x * 128;
    const int n0 = blockIdx.y * 64;

    wmma::fragment<wmma::accumulator, 16, 16, 8, float> acc[2][2];
#pragma unroll
    for (int mi = 0; mi < 2; mi++)
#pragma unroll
        for (int ni = 0; ni < 2; ni++) wmma::fill_fragment(acc[mi][ni], 0.f);

    for (int kk = 0; kk < C; kk += 32) {
        __syncthreads();
#pragma unroll
        for (int i = 0; i < 4; i++) {
            int f = tid + 256 * i; int row = f >> 3; int c4 = f & 7;
            *(float4*)&As[row][c4 * 4] = *(const float4*)(qf + (size_t)(m0 + row) * C + kk + c4 * 4);
        }
#pragma unroll
        for (int i = 0; i < 2; i++) {
            int f = tid + 256 * i; int row = f >> 4; int c4 = f & 15;
            *(float4*)&Bs[row][c4 * 4] = *(const float4*)(B + (size_t)(kk + row) * HCONF + n0 + c4 * 4);
        }
        __syncthreads();

#pragma unroll
        for (int s = 0; s < 4; s++) {
            wmma::fragment<wmma::matrix_a, 16, 16, 8, wmma::precision::tf32, wmma::row_major> af[2];
            wmma::fragment<wmma::matrix_b, 16, 16, 8, wmma::precision::tf32, wmma::row_major> bf[2];
#pragma unroll
            for (int mi = 0; mi < 2; mi++) {
                wmma::load_matrix_sync(af[mi], &As[wm * 32 + mi * 16][s * 8], A_LD);
#pragma unroll
                for (int t = 0; t < af[mi].num_elements; t++)
                    af[mi].x[t] = wmma::__float_to_tf32(af[mi].x[t]);
            }
#pragma unroll
            for (int ni = 0; ni < 2; ni++) {
                wmma::load_matrix_sync(bf[ni], &Bs[s * 8][wn * 32 + ni * 16], B_LD);
#pragma unroll
                for (int t = 0; t < bf[ni].num_elements; t++)
                    bf[ni].x[t] = wmma::__float_to_tf32(bf[ni].x[t]);
            }
#pragma unroll
            for (int mi = 0; mi < 2; mi++)
#pragma unroll
                for (int ni = 0; ni < 2; ni++)
                    wmma::mma_sync(acc[mi][ni], af[mi], bf[ni], acc[mi][ni]);
        }
    }

#pragma unroll
    for (int mi = 0; mi < 2; mi++)
#pragma unroll
        for (int ni = 0; ni < 2; ni++)
            wmma::store_matrix_sync(
                g_hq + (size_t)(m0 + wm * 32 + mi * 16) * HCONF + n0 + wn * 32 + ni * 16,
                acc[mi][ni], HCONF, wmma::mem_row_major);
}

// ---------------- conf (R1 proven) ----------------
__global__ void conf_kernel(const float* __restrict__ Wc2, const float* __restrict__ bc1,
                            const float* __restrict__ bc2) {
    __shared__ float s_hp[KP][HCONF];
    __shared__ float s_part[8][KP];
    const int tid  = threadIdx.x;
    const int lane = tid & 31;
    const int warp = tid >> 5;

    float* hpflat = &s_hp[0][0];
#pragma unroll
    for (int r = 0; r < 32; r++) hpflat[tid + 256 * r] = g_hp[tid + 256 * r];

    float wc2r[8], bcr[8];
#pragma unroll
    for (int j = 0; j < 8; j++) {
        wc2r[j] = Wc2[lane + 32 * j];
        bcr[j]  = bc1[lane + 32 * j];
    }
    const float bc2v = bc2[0];
    __syncthreads();

    float conf_acc = 0.f;
    const int nwarps = gridDim.x * 8;
    for (int q = blockIdx.x * 8 + warp; q < NQ; q += nwarps) {
        float a[8];
#pragma unroll
        for (int j = 0; j < 8; j++) a[j] = g_hq[(size_t)q * HCONF + lane + 32 * j] + bcr[j];
#pragma unroll 4
        for (int k = 0; k < KP; k++) {
            float s = 0.f;
#pragma unroll
            for (int j = 0; j < 8; j++) {
                float t = fmaxf(s_hp[k][lane + 32 * j] + a[j], 0.f);
                s = fmaf(t, wc2r[j], s);
            }
            s += __shfl_xor_sync(0xffffffffu, s, 16);
            s += __shfl_xor_sync(0xffffffffu, s, 8);
            s += __shfl_xor_sync(0xffffffffu, s, 4);
            s += __shfl_xor_sync(0xffffffffu, s, 2);
            s += __shfl_xor_sync(0xffffffffu, s, 1);
            const float sig = 1.0f / (1.0f + __expf(-(s + bc2v)));
            if (k == lane) conf_acc += sig;
        }
    }
    s_part[warp][lane] = conf_acc;
    __syncthreads();
    if (tid < KP) {
        float t = 0.f;
#pragma unroll
        for (int w = 0; w < 8; w++) t += s_part[w][tid];
        atomicAdd(&g_conf[tid], t);
    }
}

__global__ void conf_fin_kernel(float* __restrict__ out) {
    int tid = threadIdx.x;
    if (tid < KP) out[KP * C + tid] = g_conf[tid] * (1.0f / (float)NQ);
}

// ---------------- launch ----------------
extern "C" void kernel_launch(void* const* d_in, const int* in_sizes, int n_in,
                              void* d_out, int out_size) {
    const float* proto = (const float*)d_in[0];
    const float* qf    = (const float*)d_in[1];
    const float* qd    = (const float*)d_in[2];
    const float* W1    = (const float*)d_in[3];
    const float* b1    = (const float*)d_in[4];
    const float* W2    = (const float*)d_in[5];
    const float* b2    = (const float*)d_in[6];
    const float* Wc1   = (const float*)d_in[7];
    const float* bc1   = (const float*)d_in[8];
    const float* Wc2   = (const float*)d_in[9];
    const float* bc2   = (const float*)d_in[10];
    float* out = (float*)d_out;

    const int WM_SMEM = 256 * SOFT_LD * 4 + KP * C * 4;   // 40960 + 65536 = 106496
    static int smem_set = 0;
    if (!smem_set) {
        cudaFuncSetAttribute(wmean_tc_kernel, cudaFuncAttributeMaxDynamicSharedMemorySize, WM_SMEM);
        smem_set = 1;
    }

    init_kernel<<<192, 256>>>(proto, out);
    wmean_tc_kernel<<<dim3(NQ / 256, NSTEPS), 256, WM_SMEM>>>(qd, qf);
    wmean_fin_kernel<<<192, 256>>>();
    for (int t = 0; t < NSTEPS; t++) {
        gemm1_kernel<<<dim3(HREF / 64, 1024 / 64), 256>>>(out, W1, t);
        gemm2_kernel<<<dim3(C / 64, HREF / 32), 256>>>(out, W2, b1, b2, t);
    }
    hp_kernel<<<dim3(HCONF / 64, C / 32), 256>>>(proto, Wc1);
    hq_kernel<<<dim3(NQ / 128, HCONF / 64), 256>>>(qf, Wc1);
    conf_kernel<<<256, 256>>>(Wc2, bc1, bc2);
    conf_fin_kernel<<<1, 32>>>(out);
}